// round 3
// baseline (speedup 1.0000x reference)
#include <cuda_runtime.h>
#include <cstdint>
#include <math.h>

#define Bdim 64
#define Tdim 512
#define IDIM 512
#define Hdim 512
#define Odim 512

// ---- cluster scan config ----
#define CSIZE 16            // CTAs per cluster
#define NCLUST 8            // clusters (8 batches each)
#define RPB2 32             // rows per CTA (512 / 16)
#define BPC 8               // batches per cluster
#define NBLK2 (CSIZE * NCLUST)

// ---- fallback (grid-barrier) config ----
#define NBLK 128
#define RPB  16
#define BPB  16

// Scratch: xin[b,t,h] (64 MB). __device__ global => no allocation.
__device__ float g_xin[(size_t)Bdim * Tdim * Hdim];

// Grid barrier state (fallback path)
__device__ unsigned g_count = 0;
__device__ unsigned g_gen = 0;

__device__ __forceinline__ void gridbar() {
    __syncthreads();
    if (threadIdx.x == 0) {
        unsigned gen = *(volatile unsigned*)&g_gen;
        __threadfence();
        unsigned arr = atomicAdd(&g_count, 1u);
        if (arr == NBLK - 1) {
            *(volatile unsigned*)&g_count = 0u;
            __threadfence();
            atomicAdd(&g_gen, 1u);
        } else {
            while (*(volatile unsigned*)&g_gen == gen) { __nanosleep(64); }
        }
        __threadfence();
    }
    __syncthreads();
}

__device__ __forceinline__ uint32_t smem_u32(const void* p) {
    uint32_t a;
    asm("{ .reg .u64 t; cvta.to.shared.u64 t, %1; cvt.u32.u64 %0, t; }"
        : "=r"(a) : "l"(p));
    return a;
}

__device__ __forceinline__ void cluster_sync() {
    asm volatile("barrier.cluster.arrive.aligned;" ::: "memory");
    asm volatile("barrier.cluster.wait.aligned;" ::: "memory");
}

// Push one scalar to the same SMEM offset in every CTA of the cluster.
__device__ __forceinline__ void push_all(uint32_t laddr, float v) {
#pragma unroll
    for (int pr = 0; pr < CSIZE; pr++) {
        uint32_t raddr;
        asm volatile("mapa.shared::cluster.u32 %0, %1, %2;"
                     : "=r"(raddr) : "r"(laddr), "r"(pr));
        asm volatile("st.shared::cluster.f32 [%0], %1;"
                     :: "r"(raddr), "f"(v) : "memory");
    }
}

// ---------------------------------------------------------------------------
// Kernel A: g_xin[m, h] = sum_i emb[m, i] * W_in[h, i] + b_in[h]
// ---------------------------------------------------------------------------
#define BM 64
#define BN 64
#define BK 16

__global__ __launch_bounds__(256) void gemm_xin(const float* __restrict__ A,
                                                const float* __restrict__ W,
                                                const float* __restrict__ bias) {
    __shared__ float Ast[BK][BM + 4];
    __shared__ float Bst[BK][BN + 4];
    const int bn = blockIdx.x;
    const int bm = blockIdx.y;
    const int tid = threadIdx.x;

    const int lr = tid >> 2;
    const int lc = (tid & 3) << 2;
    const int tx = tid & 15;
    const int ty = tid >> 4;

    float acc[4][4];
#pragma unroll
    for (int i = 0; i < 4; i++)
#pragma unroll
        for (int j = 0; j < 4; j++) acc[i][j] = 0.0f;

    const float* Ab = A + (size_t)(bm * BM) * IDIM;
    const float* Wb = W + (size_t)(bn * BN) * IDIM;

    for (int kt = 0; kt < IDIM; kt += BK) {
        float4 av = *(const float4*)(Ab + (size_t)lr * IDIM + kt + lc);
        float4 wv = *(const float4*)(Wb + (size_t)lr * IDIM + kt + lc);
        Ast[lc + 0][lr] = av.x; Ast[lc + 1][lr] = av.y;
        Ast[lc + 2][lr] = av.z; Ast[lc + 3][lr] = av.w;
        Bst[lc + 0][lr] = wv.x; Bst[lc + 1][lr] = wv.y;
        Bst[lc + 2][lr] = wv.z; Bst[lc + 3][lr] = wv.w;
        __syncthreads();
#pragma unroll
        for (int kk = 0; kk < BK; kk++) {
            float4 a4 = *(const float4*)&Ast[kk][ty * 4];
            float4 b4 = *(const float4*)&Bst[kk][tx * 4];
            acc[0][0] = fmaf(a4.x, b4.x, acc[0][0]);
            acc[0][1] = fmaf(a4.x, b4.y, acc[0][1]);
            acc[0][2] = fmaf(a4.x, b4.z, acc[0][2]);
            acc[0][3] = fmaf(a4.x, b4.w, acc[0][3]);
            acc[1][0] = fmaf(a4.y, b4.x, acc[1][0]);
            acc[1][1] = fmaf(a4.y, b4.y, acc[1][1]);
            acc[1][2] = fmaf(a4.y, b4.z, acc[1][2]);
            acc[1][3] = fmaf(a4.y, b4.w, acc[1][3]);
            acc[2][0] = fmaf(a4.z, b4.x, acc[2][0]);
            acc[2][1] = fmaf(a4.z, b4.y, acc[2][1]);
            acc[2][2] = fmaf(a4.z, b4.z, acc[2][2]);
            acc[2][3] = fmaf(a4.z, b4.w, acc[2][3]);
            acc[3][0] = fmaf(a4.w, b4.x, acc[3][0]);
            acc[3][1] = fmaf(a4.w, b4.y, acc[3][1]);
            acc[3][2] = fmaf(a4.w, b4.z, acc[3][2]);
            acc[3][3] = fmaf(a4.w, b4.w, acc[3][3]);
        }
        __syncthreads();
    }

    const int n0 = bn * BN + tx * 4;
    float4 bsv = *(const float4*)&bias[n0];
#pragma unroll
    for (int i = 0; i < 4; i++) {
        int m = bm * BM + ty * 4 + i;
        float4 o;
        o.x = acc[i][0] + bsv.x;
        o.y = acc[i][1] + bsv.y;
        o.z = acc[i][2] + bsv.z;
        o.w = acc[i][3] + bsv.w;
        *(float4*)&g_xin[(size_t)m * Hdim + n0] = o;
    }
}

// ---------------------------------------------------------------------------
// Shared matvec tile: warp computes 4 batches x 8 rows; lanes split K.
// After tree reduce, lane kc holds dot for (i2 = kc>>3 batch, p = kc&7 row).
// ---------------------------------------------------------------------------
__device__ __forceinline__ float matvec_tile(const float* __restrict__ sW,
                                             const float* __restrict__ sA,
                                             int kc, int bg2, int rg2) {
    const float* wp = sW + (rg2 * 8) * 512 + kc;
    const float* ap = sA + (bg2 * 4) * 512 + kc;
    float acc[32];
#pragma unroll
    for (int a = 0; a < 32; a++) acc[a] = 0.0f;
#pragma unroll
    for (int j = 0; j < 16; j++) {
        const int k = 32 * j;
        float yv[4], wv[8];
#pragma unroll
        for (int i2 = 0; i2 < 4; i2++) yv[i2] = ap[i2 * 512 + k];
#pragma unroll
        for (int p = 0; p < 8; p++) wv[p] = wp[p * 512 + k];
#pragma unroll
        for (int i2 = 0; i2 < 4; i2++)
#pragma unroll
            for (int p = 0; p < 8; p++)
                acc[i2 * 8 + p] = fmaf(yv[i2], wv[p], acc[i2 * 8 + p]);
    }
#pragma unroll
    for (int s = 16; s >= 1; s >>= 1) {
        const bool up = (kc & s);
#pragma unroll
        for (int a = 0; a < s; a++) {
            float send = up ? acc[a] : acc[a + s];
            float recv = __shfl_xor_sync(0xffffffffu, send, s);
            acc[a] = (up ? acc[a + s] : acc[a]) + recv;
        }
    }
    return acc[0];
}

extern __shared__ float smem[];

// ---------------------------------------------------------------------------
// Kernel B (primary): cluster scan. 8 clusters x 16 CTAs.
// Cluster owns 8 batches; CTA owns 32 rows of W_y and W_out.
// Activation exchange via DSMEM push + barrier.cluster.
// ---------------------------------------------------------------------------
__global__ __launch_bounds__(256, 1) void jordan_scan_cluster(
    const float* __restrict__ last_logits,
    const float* __restrict__ W_y, const float* __restrict__ b_y,
    const float* __restrict__ W_out, const float* __restrict__ b_out,
    float* __restrict__ out_h, float* __restrict__ out_y,
    float* __restrict__ out_ylast) {
    float* sWy  = smem;                              // 32*512
    float* sWo  = smem + RPB2 * 512;                 // 32*512
    float* yBuf = smem + 2 * RPB2 * 512;             // 8*512
    float* hBuf = smem + 2 * RPB2 * 512 + BPC * 512; // 8*512

    const int tid = threadIdx.x;
    unsigned rank;
    asm("mov.u32 %0, %%cluster_ctarank;" : "=r"(rank));
    const int cid = blockIdx.x / CSIZE;  // cluster id 0..7
    const int b0 = cid * BPC;
    const int r0 = (int)rank * RPB2;

    // Preload this CTA's weight slices (persist all steps).
    for (int q = tid; q < RPB2 * 512 / 4; q += 256) {
        ((float4*)sWy)[q] = ((const float4*)(W_y + (size_t)r0 * 512))[q];
        ((float4*)sWo)[q] = ((const float4*)(W_out + (size_t)r0 * 512))[q];
    }
    // Stage initial y (each CTA loads its cluster's 8 batches).
    for (int q = tid; q < BPC * 512 / 4; q += 256) {
        ((float4*)yBuf)[q] = ((const float4*)(last_logits + (size_t)b0 * 512))[q];
    }

    const int w = tid >> 5, kc = tid & 31;
    const int bg2 = w & 1;        // batch half: 4 batches
    const int rg2 = w >> 1;       // row group: 8 rows (0..3)
    const int i2 = kc >> 3, p = kc & 7;
    const int bl = bg2 * 4 + i2;            // local batch 0..7
    const int rl = rg2 * 8 + p;             // local row 0..31
    const int b_idx = b0 + bl;
    const int r_idx = r0 + rl;
    const float by_v = b_y[r_idx];
    const float bo_v = b_out[r_idx];

    const uint32_t h_laddr = smem_u32(&hBuf[bl * 512 + r_idx]);
    const uint32_t y_laddr = smem_u32(&yBuf[bl * 512 + r_idx]);

    __syncthreads();
    cluster_sync();  // everyone staged before pushes can land anywhere

    float xin_cur = g_xin[((size_t)b_idx * Tdim + 0) * Hdim + r_idx];

    for (int t = 0; t < Tdim; t++) {
        // ---- GEMM1: h = tanh(xin + y_prev @ W_y^T + b_y) ----
        float v = matvec_tile(sWy, yBuf, kc, bg2, rg2);
        v += xin_cur + by_v;
        v = tanhf(v);
        out_h[((size_t)b_idx * Tdim + t) * Hdim + r_idx] = v;

        // prefetch next xin (consumed one full step later)
        if (t + 1 < Tdim)
            xin_cur = g_xin[((size_t)b_idx * Tdim + (t + 1)) * Hdim + r_idx];

        push_all(h_laddr, v);
        cluster_sync();

        // ---- GEMM2: y = h @ W_out^T + b_out ----
        float u = matvec_tile(sWo, hBuf, kc, bg2, rg2);
        u += bo_v;
        out_y[((size_t)b_idx * Tdim + t) * Odim + r_idx] = u;
        if (t == Tdim - 1)
            out_ylast[(size_t)b_idx * Odim + r_idx] = u;

        push_all(y_laddr, u);
        cluster_sync();
    }
}

// ---------------------------------------------------------------------------
// Kernel B (fallback): grid-barrier scan (Round-1 design).
// ---------------------------------------------------------------------------
__global__ __launch_bounds__(256, 1) void jordan_scan(
    const float* __restrict__ last_logits,
    const float* __restrict__ W_y, const float* __restrict__ b_y,
    const float* __restrict__ W_out, const float* __restrict__ b_out,
    float* __restrict__ out_h, float* __restrict__ out_y,
    float* __restrict__ out_ylast) {
    float* sWy  = smem;
    float* sWo  = smem + RPB * 512;
    float* sAct = smem + 2 * RPB * 512;

    const int tid = threadIdx.x;
    const int bid = blockIdx.x;
    const int rg = bid & 31;
    const int bg = bid >> 5;
    const int r0 = rg * RPB;
    const int b0 = bg * BPB;

    for (int q = tid; q < RPB * 512 / 4; q += 256) {
        ((float4*)sWy)[q] = ((const float4*)(W_y + (size_t)r0 * 512))[q];
        ((float4*)sWo)[q] = ((const float4*)(W_out + (size_t)r0 * 512))[q];
    }

    const int w = tid >> 5, kc = tid & 31;
    const int bg2 = w >> 1, rg2 = w & 1;
    const int i2 = kc >> 3, p = kc & 7;
    const int b_out_idx = b0 + bg2 * 4 + i2;
    const int r_out_idx = r0 + rg2 * 8 + p;
    const float by_v = b_y[r_out_idx];
    const float bo_v = b_out[r_out_idx];

    const int sb = tid >> 4;
    const int sc = tid & 15;

    __syncthreads();

    for (int t = 0; t < Tdim; t++) {
        {
            const float* src = (t == 0)
                ? last_logits + (size_t)(b0 + sb) * Odim
                : out_y + ((size_t)(b0 + sb) * Tdim + (t - 1)) * Odim;
            float4* dst = (float4*)(sAct + sb * 512);
            const float4* s4 = (const float4*)src;
#pragma unroll
            for (int q = 0; q < 8; q++) dst[sc + 16 * q] = s4[sc + 16 * q];
        }
        __syncthreads();

        {
            float v = matvec_tile(sWy, sAct, kc, bg2, rg2);
            v += g_xin[((size_t)b_out_idx * Tdim + t) * Hdim + r_out_idx] + by_v;
            v = tanhf(v);
            out_h[((size_t)b_out_idx * Tdim + t) * Hdim + r_out_idx] = v;
        }
        __threadfence();
        gridbar();

        {
            const float* src = out_h + ((size_t)(b0 + sb) * Tdim + t) * Hdim;
            float4* dst = (float4*)(sAct + sb * 512);
            const float4* s4 = (const float4*)src;
#pragma unroll
            for (int q = 0; q < 8; q++) dst[sc + 16 * q] = s4[sc + 16 * q];
        }
        __syncthreads();

        {
            float v = matvec_tile(sWo, sAct, kc, bg2, rg2);
            v += bo_v;
            out_y[((size_t)b_out_idx * Tdim + t) * Odim + r_out_idx] = v;
            if (t == Tdim - 1) out_ylast[(size_t)b_out_idx * Odim + r_out_idx] = v;
        }
        __threadfence();
        gridbar();
    }
}

// ---------------------------------------------------------------------------
extern "C" void kernel_launch(void* const* d_in, const int* in_sizes, int n_in,
                              void* d_out, int out_size) {
    const float* emb    = (const float*)d_in[0];
    const float* lastlg = (const float*)d_in[1];
    const float* W_in   = (const float*)d_in[2];
    const float* b_in   = (const float*)d_in[3];
    const float* W_y    = (const float*)d_in[4];
    const float* b_y    = (const float*)d_in[5];
    const float* W_out  = (const float*)d_in[6];
    const float* b_out  = (const float*)d_in[7];

    float* out    = (float*)d_out;
    float* out_h  = out;
    float* out_y  = out + (size_t)Bdim * Tdim * Hdim;
    float* out_yl = out + (size_t)2 * Bdim * Tdim * Hdim;

    dim3 gA(Hdim / BN, (Bdim * Tdim) / BM);
    gemm_xin<<<gA, 256>>>(emb, W_in, b_in);

    // ---- try cluster path ----
    const int smem_cluster = (2 * RPB2 * 512 + 2 * BPC * 512) * (int)sizeof(float); // 160 KB
    bool use_cluster = true;
    if (cudaFuncSetAttribute(jordan_scan_cluster,
                             cudaFuncAttributeMaxDynamicSharedMemorySize,
                             smem_cluster) != cudaSuccess)
        use_cluster = false;
    if (use_cluster &&
        cudaFuncSetAttribute(jordan_scan_cluster,
                             cudaFuncAttributeNonPortableClusterSizeAllowed,
                             1) != cudaSuccess)
        use_cluster = false;

    cudaLaunchConfig_t cfg = {};
    cfg.gridDim = dim3(NBLK2, 1, 1);
    cfg.blockDim = dim3(256, 1, 1);
    cfg.dynamicSmemBytes = smem_cluster;
    cudaLaunchAttribute attrs[1];
    attrs[0].id = cudaLaunchAttributeClusterDimension;
    attrs[0].val.clusterDim.x = CSIZE;
    attrs[0].val.clusterDim.y = 1;
    attrs[0].val.clusterDim.z = 1;
    cfg.attrs = attrs;
    cfg.numAttrs = 1;

    if (use_cluster) {
        int maxClusters = 0;
        cudaError_t st = cudaOccupancyMaxActiveClusters(&maxClusters,
                                                        jordan_scan_cluster, &cfg);
        if (st != cudaSuccess || maxClusters < NCLUST) use_cluster = false;
    }
    (void)cudaGetLastError();  // clear any probe error state

    if (use_cluster) {
        cudaLaunchKernelEx(&cfg, jordan_scan_cluster, lastlg, W_y, b_y, W_out,
                           b_out, out_h, out_y, out_yl);
    } else {
        const int smem_fb = 3 * RPB * 512 * (int)sizeof(float);  // 96 KB
        cudaFuncSetAttribute(jordan_scan,
                             cudaFuncAttributeMaxDynamicSharedMemorySize, smem_fb);
        jordan_scan<<<NBLK, 256, smem_fb>>>(lastlg, W_y, b_y, W_out, b_out,
                                            out_h, out_y, out_yl);
    }
}

// round 4
// speedup vs baseline: 1.4385x; 1.4385x over previous
#include <cuda_runtime.h>
#include <cstdint>
#include <math.h>

#define Bdim 64
#define Tdim 512
#define IDIM 512
#define Hdim 512
#define Odim 512

// ---- cluster scan config (portable cluster size 8) ----
#define CSZ 8               // CTAs per cluster
#define NCL 16              // clusters (4 batches each)
#define ROWS_C 64           // rows of M per CTA
#define BPCL 4              // batches per cluster

// ---- fallback (grid-barrier) config ----
#define NBLK 128
#define RPB  16
#define BPB  16

// Device scratch (no allocations allowed)
__device__ float g_xin[(size_t)Bdim * Tdim * Hdim];  // 64 MB
__device__ float g_M[512 * 512];                     // W_y @ W_out
__device__ float g_r0[Bdim * 512];                   // last_logits @ W_y^T + b_y
__device__ float g_c[512];                           // W_y b_out + b_y

// Grid barrier state (fallback path)
__device__ unsigned g_count = 0;
__device__ unsigned g_gen = 0;

__device__ __forceinline__ void gridbar() {
    __syncthreads();
    if (threadIdx.x == 0) {
        unsigned gen = *(volatile unsigned*)&g_gen;
        __threadfence();
        unsigned arr = atomicAdd(&g_count, 1u);
        if (arr == NBLK - 1) {
            *(volatile unsigned*)&g_count = 0u;
            __threadfence();
            atomicAdd(&g_gen, 1u);
        } else {
            while (*(volatile unsigned*)&g_gen == gen) { __nanosleep(64); }
        }
        __threadfence();
    }
    __syncthreads();
}

__device__ __forceinline__ uint32_t smem_u32(const void* p) {
    uint32_t a;
    asm("{ .reg .u64 t; cvta.to.shared.u64 t, %1; cvt.u32.u64 %0, t; }"
        : "=r"(a) : "l"(p));
    return a;
}

__device__ __forceinline__ void cluster_sync() {
    asm volatile("barrier.cluster.arrive.aligned;" ::: "memory");
    asm volatile("barrier.cluster.wait.aligned;" ::: "memory");
}

// Push one scalar to the same SMEM offset in every CTA of an 8-CTA cluster.
__device__ __forceinline__ void push_all8(uint32_t laddr, float v) {
#pragma unroll
    for (int pr = 0; pr < CSZ; pr++) {
        uint32_t raddr;
        asm volatile("mapa.shared::cluster.u32 %0, %1, %2;"
                     : "=r"(raddr) : "r"(laddr), "r"(pr));
        asm volatile("st.shared::cluster.f32 [%0], %1;"
                     :: "r"(raddr), "f"(v) : "memory");
    }
}

// ---------------------------------------------------------------------------
// Generic NT SGEMM: C[m,n] = sum_k A[m,k]*W[n,k] + bias[n].  N=K=512 fixed.
// If ylast != nullptr, rows with (m % Tdim == Tdim-1) also write
// ylast[(m/Tdim)*512 + n].
// ---------------------------------------------------------------------------
#define BM 64
#define BN 64
#define BK 16

__global__ __launch_bounds__(256) void gemm_nt(const float* __restrict__ A,
                                               const float* __restrict__ W,
                                               const float* __restrict__ bias,
                                               float* __restrict__ C,
                                               float* __restrict__ ylast) {
    __shared__ float Ast[BK][BM + 4];
    __shared__ float Bst[BK][BN + 4];
    const int bn = blockIdx.x;
    const int bm = blockIdx.y;
    const int tid = threadIdx.x;

    const int lr = tid >> 2;
    const int lc = (tid & 3) << 2;
    const int tx = tid & 15;
    const int ty = tid >> 4;

    float acc[4][4];
#pragma unroll
    for (int i = 0; i < 4; i++)
#pragma unroll
        for (int j = 0; j < 4; j++) acc[i][j] = 0.0f;

    const float* Ab = A + (size_t)(bm * BM) * 512;
    const float* Wb = W + (size_t)(bn * BN) * 512;

    for (int kt = 0; kt < 512; kt += BK) {
        float4 av = *(const float4*)(Ab + (size_t)lr * 512 + kt + lc);
        float4 wv = *(const float4*)(Wb + (size_t)lr * 512 + kt + lc);
        Ast[lc + 0][lr] = av.x; Ast[lc + 1][lr] = av.y;
        Ast[lc + 2][lr] = av.z; Ast[lc + 3][lr] = av.w;
        Bst[lc + 0][lr] = wv.x; Bst[lc + 1][lr] = wv.y;
        Bst[lc + 2][lr] = wv.z; Bst[lc + 3][lr] = wv.w;
        __syncthreads();
#pragma unroll
        for (int kk = 0; kk < BK; kk++) {
            float4 a4 = *(const float4*)&Ast[kk][ty * 4];
            float4 b4 = *(const float4*)&Bst[kk][tx * 4];
            acc[0][0] = fmaf(a4.x, b4.x, acc[0][0]);
            acc[0][1] = fmaf(a4.x, b4.y, acc[0][1]);
            acc[0][2] = fmaf(a4.x, b4.z, acc[0][2]);
            acc[0][3] = fmaf(a4.x, b4.w, acc[0][3]);
            acc[1][0] = fmaf(a4.y, b4.x, acc[1][0]);
            acc[1][1] = fmaf(a4.y, b4.y, acc[1][1]);
            acc[1][2] = fmaf(a4.y, b4.z, acc[1][2]);
            acc[1][3] = fmaf(a4.y, b4.w, acc[1][3]);
            acc[2][0] = fmaf(a4.z, b4.x, acc[2][0]);
            acc[2][1] = fmaf(a4.z, b4.y, acc[2][1]);
            acc[2][2] = fmaf(a4.z, b4.z, acc[2][2]);
            acc[2][3] = fmaf(a4.z, b4.w, acc[2][3]);
            acc[3][0] = fmaf(a4.w, b4.x, acc[3][0]);
            acc[3][1] = fmaf(a4.w, b4.y, acc[3][1]);
            acc[3][2] = fmaf(a4.w, b4.z, acc[3][2]);
            acc[3][3] = fmaf(a4.w, b4.w, acc[3][3]);
        }
        __syncthreads();
    }

    const int n0 = bn * BN + tx * 4;
    float4 bsv = *(const float4*)&bias[n0];
#pragma unroll
    for (int i = 0; i < 4; i++) {
        int m = bm * BM + ty * 4 + i;
        float4 o;
        o.x = acc[i][0] + bsv.x;
        o.y = acc[i][1] + bsv.y;
        o.z = acc[i][2] + bsv.z;
        o.w = acc[i][3] + bsv.w;
        *(float4*)&C[(size_t)m * 512 + n0] = o;
        if (ylast != nullptr && (m & (Tdim - 1)) == (Tdim - 1)) {
            *(float4*)&ylast[(size_t)(m >> 9) * 512 + n0] = o;
        }
    }
}

// ---------------------------------------------------------------------------
// NN SGEMM for M = W_y @ W_out (512x512x512).
// ---------------------------------------------------------------------------
__global__ __launch_bounds__(256) void gemm_nn_M(const float* __restrict__ A,
                                                 const float* __restrict__ B,
                                                 float* __restrict__ C) {
    __shared__ float Ast[BK][BM + 4];
    __shared__ float Bst[BK][BN + 4];
    const int bn = blockIdx.x;
    const int bm = blockIdx.y;
    const int tid = threadIdx.x;

    const int ar = tid >> 2;
    const int ak = (tid & 3) << 2;
    const int br = tid >> 4;          // 0..15
    const int bc = (tid & 15) << 2;   // 0..60
    const int tx = tid & 15;
    const int ty = tid >> 4;

    float acc[4][4];
#pragma unroll
    for (int i = 0; i < 4; i++)
#pragma unroll
        for (int j = 0; j < 4; j++) acc[i][j] = 0.0f;

    for (int kt = 0; kt < 512; kt += BK) {
        float4 av = *(const float4*)(A + (size_t)(bm * BM + ar) * 512 + kt + ak);
        Ast[ak + 0][ar] = av.x; Ast[ak + 1][ar] = av.y;
        Ast[ak + 2][ar] = av.z; Ast[ak + 3][ar] = av.w;
        float4 bv = *(const float4*)(B + (size_t)(kt + br) * 512 + bn * BN + bc);
        *(float4*)&Bst[br][bc] = bv;
        __syncthreads();
#pragma unroll
        for (int kk = 0; kk < BK; kk++) {
            float4 a4 = *(const float4*)&Ast[kk][ty * 4];
            float4 b4 = *(const float4*)&Bst[kk][tx * 4];
#pragma unroll
            for (int i = 0; i < 4; i++) {
                float av_ = (&a4.x)[i];
                acc[i][0] = fmaf(av_, b4.x, acc[i][0]);
                acc[i][1] = fmaf(av_, b4.y, acc[i][1]);
                acc[i][2] = fmaf(av_, b4.z, acc[i][2]);
                acc[i][3] = fmaf(av_, b4.w, acc[i][3]);
            }
        }
        __syncthreads();
    }

    const int n0 = bn * BN + tx * 4;
#pragma unroll
    for (int i = 0; i < 4; i++) {
        int m = bm * BM + ty * 4 + i;
        float4 o = make_float4(acc[i][0], acc[i][1], acc[i][2], acc[i][3]);
        *(float4*)&C[(size_t)m * 512 + n0] = o;
    }
}

// c[i] = b_y[i] + dot(W_y[i,:], b_out)
__global__ void calc_c_kernel(const float* __restrict__ W_y,
                              const float* __restrict__ b_y,
                              const float* __restrict__ b_out,
                              float* __restrict__ c) {
    int row = blockIdx.x * 8 + (threadIdx.x >> 5);
    int l = threadIdx.x & 31;
    float s = 0.0f;
    for (int j = l; j < 512; j += 32) s += W_y[row * 512 + j] * b_out[j];
#pragma unroll
    for (int off = 16; off; off >>= 1) s += __shfl_xor_sync(0xffffffffu, s, off);
    if (l == 0) c[row] = s + b_y[row];
}

// ---------------------------------------------------------------------------
// Warp matvec tile: 8 rows x 4 batches, lanes split K (32-way).
// After tree reduce, lane kc holds dot for (batch kc>>3, row kc&7).
// ---------------------------------------------------------------------------
__device__ __forceinline__ float matvec_tile(const float* __restrict__ sW,
                                             const float* __restrict__ sA,
                                             int kc, int bg2, int rg2) {
    const float* wp = sW + (rg2 * 8) * 512 + kc;
    const float* ap = sA + (bg2 * 4) * 512 + kc;
    float acc[32];
#pragma unroll
    for (int a = 0; a < 32; a++) acc[a] = 0.0f;
#pragma unroll
    for (int j = 0; j < 16; j++) {
        const int k = 32 * j;
        float yv[4], wv[8];
#pragma unroll
        for (int i2 = 0; i2 < 4; i2++) yv[i2] = ap[i2 * 512 + k];
#pragma unroll
        for (int p = 0; p < 8; p++) wv[p] = wp[p * 512 + k];
#pragma unroll
        for (int i2 = 0; i2 < 4; i2++)
#pragma unroll
            for (int p = 0; p < 8; p++)
                acc[i2 * 8 + p] = fmaf(yv[i2], wv[p], acc[i2 * 8 + p]);
    }
#pragma unroll
    for (int s = 16; s >= 1; s >>= 1) {
        const bool up = (kc & s);
#pragma unroll
        for (int a = 0; a < s; a++) {
            float send = up ? acc[a] : acc[a + s];
            float recv = __shfl_xor_sync(0xffffffffu, send, s);
            acc[a] = (up ? acc[a + s] : acc[a]) + recv;
        }
    }
    return acc[0];
}

extern __shared__ float smem[];

// ---------------------------------------------------------------------------
// Primary scan: h_t = tanh(xin_t + M h_{t-1} + c), 16 clusters x 8 CTAs.
// Cluster owns 4 batches; CTA owns 64 rows of M (128 KB SMEM).
// Double-buffered DSMEM h exchange, ONE cluster sync per step.
// ---------------------------------------------------------------------------
__global__ __launch_bounds__(256, 1) void jordan_scan_m_cluster(
    float* __restrict__ out_h) {
    float* sM    = smem;                       // 64*512
    float* hbuf0 = smem + ROWS_C * 512;        // 4*512
    float* hbuf1 = hbuf0 + BPCL * 512;         // 4*512

    const int tid = threadIdx.x;
    unsigned rank;
    asm("mov.u32 %0, %%cluster_ctarank;" : "=r"(rank));
    const int cid = blockIdx.x / CSZ;
    const int b0 = cid * BPCL;
    const int r0row = (int)rank * ROWS_C;

    // Load this CTA's M slice.
    for (int q = tid; q < ROWS_C * 512 / 4; q += 256)
        ((float4*)sM)[q] = ((const float4*)(g_M + (size_t)r0row * 512))[q];

    const int w = tid >> 5, kc = tid & 31;
    const int i2 = kc >> 3, p = kc & 7;
    const int bl = i2;                  // local batch 0..3
    const int rl = w * 8 + p;           // local row 0..63
    const int b_idx = b0 + bl;
    const int r_idx = r0row + rl;
    const float cv = g_c[r_idx];

    uint32_t laddr[2];
    laddr[0] = smem_u32(&hbuf0[bl * 512 + r_idx]);
    laddr[1] = smem_u32(&hbuf1[bl * 512 + r_idx]);

    __syncthreads();
    cluster_sync();

    // t = 0: h_0 = tanh(xin_0 + r0)
    float xin_cur = g_xin[((size_t)b_idx * Tdim + 0) * Hdim + r_idx];
    {
        float v = tanhf(xin_cur + g_r0[(size_t)b_idx * 512 + r_idx]);
        out_h[((size_t)b_idx * Tdim + 0) * Hdim + r_idx] = v;
        xin_cur = g_xin[((size_t)b_idx * Tdim + 1) * Hdim + r_idx];
        push_all8(laddr[0], v);
        cluster_sync();
    }

    for (int t = 1; t < Tdim; t++) {
        const float* hb = ((t & 1) == 1) ? hbuf0 : hbuf1;  // h_{t-1} parity
        float v = matvec_tile(sM, hb, kc, 0, w);
        v = tanhf(v + xin_cur + cv);
        out_h[((size_t)b_idx * Tdim + t) * Hdim + r_idx] = v;
        if (t + 1 < Tdim)
            xin_cur = g_xin[((size_t)b_idx * Tdim + (t + 1)) * Hdim + r_idx];
        push_all8(laddr[t & 1], v);
        cluster_sync();
    }
}

// ---------------------------------------------------------------------------
// Fallback scan: same recurrence, grid barrier (128 CTAs), ONE barrier/step.
// CTA = 16 batches x 16 rows; h staged from global each step.
// ---------------------------------------------------------------------------
__global__ __launch_bounds__(256, 1) void jordan_scan_m(
    float* __restrict__ out_h) {
    float* sM   = smem;                 // 16*512
    float* sAct = smem + RPB * 512;     // 16*512

    const int tid = threadIdx.x;
    const int bid = blockIdx.x;
    const int rg = bid & 31;
    const int bg = bid >> 5;
    const int r0 = rg * RPB;
    const int b0 = bg * BPB;

    for (int q = tid; q < RPB * 512 / 4; q += 256)
        ((float4*)sM)[q] = ((const float4*)(g_M + (size_t)r0 * 512))[q];

    const int w = tid >> 5, kc = tid & 31;
    const int bg2 = w >> 1, rg2 = w & 1;
    const int i2 = kc >> 3, p = kc & 7;
    const int b_idx = b0 + bg2 * 4 + i2;
    const int r_idx = r0 + rg2 * 8 + p;
    const float cv = g_c[r_idx];

    const int sb = tid >> 4;
    const int sc = tid & 15;

    __syncthreads();

    // t = 0
    {
        float v = tanhf(g_xin[((size_t)b_idx * Tdim + 0) * Hdim + r_idx] +
                        g_r0[(size_t)b_idx * 512 + r_idx]);
        out_h[((size_t)b_idx * Tdim + 0) * Hdim + r_idx] = v;
    }
    __threadfence();
    gridbar();

    for (int t = 1; t < Tdim; t++) {
        // stage h_{t-1} for this block's 16 batches
        {
            const float* src = out_h + ((size_t)(b0 + sb) * Tdim + (t - 1)) * Hdim;
            float4* dst = (float4*)(sAct + sb * 512);
            const float4* s4 = (const float4*)src;
#pragma unroll
            for (int q = 0; q < 8; q++) dst[sc + 16 * q] = s4[sc + 16 * q];
        }
        __syncthreads();

        float v = matvec_tile(sM, sAct, kc, bg2, rg2);
        v = tanhf(v + g_xin[((size_t)b_idx * Tdim + t) * Hdim + r_idx] + cv);
        out_h[((size_t)b_idx * Tdim + t) * Hdim + r_idx] = v;
        __threadfence();
        gridbar();
    }
}

// ---------------------------------------------------------------------------
extern "C" void kernel_launch(void* const* d_in, const int* in_sizes, int n_in,
                              void* d_out, int out_size) {
    const float* emb    = (const float*)d_in[0];
    const float* lastlg = (const float*)d_in[1];
    const float* W_in   = (const float*)d_in[2];
    const float* b_in   = (const float*)d_in[3];
    const float* W_y    = (const float*)d_in[4];
    const float* b_y    = (const float*)d_in[5];
    const float* W_out  = (const float*)d_in[6];
    const float* b_out  = (const float*)d_in[7];

    float* out    = (float*)d_out;
    float* out_h  = out;
    float* out_y  = out + (size_t)Bdim * Tdim * Hdim;
    float* out_yl = out + (size_t)2 * Bdim * Tdim * Hdim;

    float* xin_p; cudaGetSymbolAddress((void**)&xin_p, g_xin);
    float* M_p;   cudaGetSymbolAddress((void**)&M_p, g_M);
    float* r0_p;  cudaGetSymbolAddress((void**)&r0_p, g_r0);
    float* c_p;   cudaGetSymbolAddress((void**)&c_p, g_c);

    // Small precomputes first
    gemm_nn_M<<<dim3(512 / BN, 512 / BM), 256>>>(W_y, W_out, M_p);
    calc_c_kernel<<<64, 256>>>(W_y, b_y, b_out, c_p);
    gemm_nt<<<dim3(512 / BN, Bdim / BM), 256>>>(lastlg, W_y, b_y, r0_p, nullptr);

    // Big input projection
    gemm_nt<<<dim3(512 / BN, (Bdim * Tdim) / BM), 256>>>(emb, W_in, b_in,
                                                          xin_p, nullptr);

    // ---- scan: try 8-CTA cluster path ----
    const int smem_cluster = (ROWS_C * 512 + 2 * BPCL * 512) * (int)sizeof(float); // 144 KB
    bool use_cluster =
        (cudaFuncSetAttribute(jordan_scan_m_cluster,
                              cudaFuncAttributeMaxDynamicSharedMemorySize,
                              smem_cluster) == cudaSuccess);

    cudaLaunchConfig_t cfg = {};
    cfg.gridDim = dim3(CSZ * NCL, 1, 1);
    cfg.blockDim = dim3(256, 1, 1);
    cfg.dynamicSmemBytes = smem_cluster;
    cudaLaunchAttribute attrs[1];
    attrs[0].id = cudaLaunchAttributeClusterDimension;
    attrs[0].val.clusterDim.x = CSZ;
    attrs[0].val.clusterDim.y = 1;
    attrs[0].val.clusterDim.z = 1;
    cfg.attrs = attrs;
    cfg.numAttrs = 1;

    if (use_cluster) {
        int maxClusters = 0;
        cudaError_t st = cudaOccupancyMaxActiveClusters(&maxClusters,
                                                        jordan_scan_m_cluster, &cfg);
        if (st != cudaSuccess || maxClusters < NCL) use_cluster = false;
    }
    (void)cudaGetLastError();

    if (use_cluster) {
        cudaLaunchKernelEx(&cfg, jordan_scan_m_cluster, out_h);
    } else {
        const int smem_fb = 2 * RPB * 512 * (int)sizeof(float);  // 64 KB
        cudaFuncSetAttribute(jordan_scan_m,
                             cudaFuncAttributeMaxDynamicSharedMemorySize, smem_fb);
        jordan_scan_m<<<NBLK, 256, smem_fb>>>(out_h);
    }

    // Epilogue: y = h @ W_out^T + b_out (+ y_last rows)
    gemm_nt<<<dim3(512 / BN, (Bdim * Tdim) / BM), 256>>>(out_h, W_out, b_out,
                                                          out_y, out_yl);
}

// round 5
// speedup vs baseline: 2.6544x; 1.8452x over previous
#include <cuda_runtime.h>
#include <cstdint>
#include <math.h>

#define Bdim 64
#define Tdim 512
#define IDIM 512
#define Hdim 512
#define Odim 512

// ---- cluster scan config (4-CTA clusters) ----
#define CSZ 4               // CTAs per cluster
#define NCL 32              // clusters (2 batches each)
#define ROWS_C 128          // rows of M per CTA
#define BPCL 2              // batches per cluster
#define KHALF 256           // K elements kept in SMEM (rest in registers)

// ---- fallback (grid-barrier) config ----
#define NBLK 128
#define RPB  16
#define BPB  16

// Device scratch (no allocations allowed)
__device__ float g_xin[(size_t)Bdim * Tdim * Hdim];  // 64 MB
__device__ float g_M[512 * 512];                     // W_y @ W_out
__device__ float g_r0[Bdim * 512];                   // last_logits @ W_y^T + b_y
__device__ float g_c[512];                           // W_y b_out + b_y

// Grid barrier state (fallback path)
__device__ unsigned g_count = 0;
__device__ unsigned g_gen = 0;

__device__ __forceinline__ void gridbar() {
    __syncthreads();
    if (threadIdx.x == 0) {
        unsigned gen = *(volatile unsigned*)&g_gen;
        __threadfence();
        unsigned arr = atomicAdd(&g_count, 1u);
        if (arr == NBLK - 1) {
            *(volatile unsigned*)&g_count = 0u;
            __threadfence();
            atomicAdd(&g_gen, 1u);
        } else {
            while (*(volatile unsigned*)&g_gen == gen) { __nanosleep(64); }
        }
        __threadfence();
    }
    __syncthreads();
}

__device__ __forceinline__ uint32_t smem_u32(const void* p) {
    uint32_t a;
    asm("{ .reg .u64 t; cvta.to.shared.u64 t, %1; cvt.u32.u64 %0, t; }"
        : "=r"(a) : "l"(p));
    return a;
}

__device__ __forceinline__ void cluster_sync() {
    asm volatile("barrier.cluster.arrive.aligned;" ::: "memory");
    asm volatile("barrier.cluster.wait.aligned;" ::: "memory");
}

// Push one scalar to the same SMEM offset in every CTA of a 4-CTA cluster.
__device__ __forceinline__ void push_all4(uint32_t laddr, float v) {
#pragma unroll
    for (int pr = 0; pr < CSZ; pr++) {
        uint32_t raddr;
        asm volatile("mapa.shared::cluster.u32 %0, %1, %2;"
                     : "=r"(raddr) : "r"(laddr), "r"(pr));
        asm volatile("st.shared::cluster.f32 [%0], %1;"
                     :: "r"(raddr), "f"(v) : "memory");
    }
}

// ---------------------------------------------------------------------------
// Generic NT SGEMM: C[m,n] = sum_k A[m,k]*W[n,k] + bias[n].  N=K=512 fixed.
// If ylast != nullptr, rows with (m % Tdim == Tdim-1) also write ylast.
// ---------------------------------------------------------------------------
#define BM 64
#define BN 64
#define BK 16

__global__ __launch_bounds__(256) void gemm_nt(const float* __restrict__ A,
                                               const float* __restrict__ W,
                                               const float* __restrict__ bias,
                                               float* __restrict__ C,
                                               float* __restrict__ ylast) {
    __shared__ float Ast[BK][BM + 4];
    __shared__ float Bst[BK][BN + 4];
    const int bn = blockIdx.x;
    const int bm = blockIdx.y;
    const int tid = threadIdx.x;

    const int lr = tid >> 2;
    const int lc = (tid & 3) << 2;
    const int tx = tid & 15;
    const int ty = tid >> 4;

    float acc[4][4];
#pragma unroll
    for (int i = 0; i < 4; i++)
#pragma unroll
        for (int j = 0; j < 4; j++) acc[i][j] = 0.0f;

    const float* Ab = A + (size_t)(bm * BM) * 512;
    const float* Wb = W + (size_t)(bn * BN) * 512;

    for (int kt = 0; kt < 512; kt += BK) {
        float4 av = *(const float4*)(Ab + (size_t)lr * 512 + kt + lc);
        float4 wv = *(const float4*)(Wb + (size_t)lr * 512 + kt + lc);
        Ast[lc + 0][lr] = av.x; Ast[lc + 1][lr] = av.y;
        Ast[lc + 2][lr] = av.z; Ast[lc + 3][lr] = av.w;
        Bst[lc + 0][lr] = wv.x; Bst[lc + 1][lr] = wv.y;
        Bst[lc + 2][lr] = wv.z; Bst[lc + 3][lr] = wv.w;
        __syncthreads();
#pragma unroll
        for (int kk = 0; kk < BK; kk++) {
            float4 a4 = *(const float4*)&Ast[kk][ty * 4];
            float4 b4 = *(const float4*)&Bst[kk][tx * 4];
            acc[0][0] = fmaf(a4.x, b4.x, acc[0][0]);
            acc[0][1] = fmaf(a4.x, b4.y, acc[0][1]);
            acc[0][2] = fmaf(a4.x, b4.z, acc[0][2]);
            acc[0][3] = fmaf(a4.x, b4.w, acc[0][3]);
            acc[1][0] = fmaf(a4.y, b4.x, acc[1][0]);
            acc[1][1] = fmaf(a4.y, b4.y, acc[1][1]);
            acc[1][2] = fmaf(a4.y, b4.z, acc[1][2]);
            acc[1][3] = fmaf(a4.y, b4.w, acc[1][3]);
            acc[2][0] = fmaf(a4.z, b4.x, acc[2][0]);
            acc[2][1] = fmaf(a4.z, b4.y, acc[2][1]);
            acc[2][2] = fmaf(a4.z, b4.z, acc[2][2]);
            acc[2][3] = fmaf(a4.z, b4.w, acc[2][3]);
            acc[3][0] = fmaf(a4.w, b4.x, acc[3][0]);
            acc[3][1] = fmaf(a4.w, b4.y, acc[3][1]);
            acc[3][2] = fmaf(a4.w, b4.z, acc[3][2]);
            acc[3][3] = fmaf(a4.w, b4.w, acc[3][3]);
        }
        __syncthreads();
    }

    const int n0 = bn * BN + tx * 4;
    float4 bsv = *(const float4*)&bias[n0];
#pragma unroll
    for (int i = 0; i < 4; i++) {
        int m = bm * BM + ty * 4 + i;
        float4 o;
        o.x = acc[i][0] + bsv.x;
        o.y = acc[i][1] + bsv.y;
        o.z = acc[i][2] + bsv.z;
        o.w = acc[i][3] + bsv.w;
        *(float4*)&C[(size_t)m * 512 + n0] = o;
        if (ylast != nullptr && (m & (Tdim - 1)) == (Tdim - 1)) {
            *(float4*)&ylast[(size_t)(m >> 9) * 512 + n0] = o;
        }
    }
}

// ---------------------------------------------------------------------------
// NN SGEMM for M = W_y @ W_out (512x512x512).
// ---------------------------------------------------------------------------
__global__ __launch_bounds__(256) void gemm_nn_M(const float* __restrict__ A,
                                                 const float* __restrict__ B,
                                                 float* __restrict__ C) {
    __shared__ float Ast[BK][BM + 4];
    __shared__ float Bst[BK][BN + 4];
    const int bn = blockIdx.x;
    const int bm = blockIdx.y;
    const int tid = threadIdx.x;

    const int ar = tid >> 2;
    const int ak = (tid & 3) << 2;
    const int br = tid >> 4;
    const int bc = (tid & 15) << 2;
    const int tx = tid & 15;
    const int ty = tid >> 4;

    float acc[4][4];
#pragma unroll
    for (int i = 0; i < 4; i++)
#pragma unroll
        for (int j = 0; j < 4; j++) acc[i][j] = 0.0f;

    for (int kt = 0; kt < 512; kt += BK) {
        float4 av = *(const float4*)(A + (size_t)(bm * BM + ar) * 512 + kt + ak);
        Ast[ak + 0][ar] = av.x; Ast[ak + 1][ar] = av.y;
        Ast[ak + 2][ar] = av.z; Ast[ak + 3][ar] = av.w;
        float4 bv = *(const float4*)(B + (size_t)(kt + br) * 512 + bn * BN + bc);
        *(float4*)&Bst[br][bc] = bv;
        __syncthreads();
#pragma unroll
        for (int kk = 0; kk < BK; kk++) {
            float4 a4 = *(const float4*)&Ast[kk][ty * 4];
            float4 b4 = *(const float4*)&Bst[kk][tx * 4];
#pragma unroll
            for (int i = 0; i < 4; i++) {
                float av_ = (&a4.x)[i];
                acc[i][0] = fmaf(av_, b4.x, acc[i][0]);
                acc[i][1] = fmaf(av_, b4.y, acc[i][1]);
                acc[i][2] = fmaf(av_, b4.z, acc[i][2]);
                acc[i][3] = fmaf(av_, b4.w, acc[i][3]);
            }
        }
        __syncthreads();
    }

    const int n0 = bn * BN + tx * 4;
#pragma unroll
    for (int i = 0; i < 4; i++) {
        int m = bm * BM + ty * 4 + i;
        float4 o = make_float4(acc[i][0], acc[i][1], acc[i][2], acc[i][3]);
        *(float4*)&C[(size_t)m * 512 + n0] = o;
    }
}

// c[i] = b_y[i] + dot(W_y[i,:], b_out)
__global__ void calc_c_kernel(const float* __restrict__ W_y,
                              const float* __restrict__ b_y,
                              const float* __restrict__ b_out,
                              float* __restrict__ c) {
    int row = blockIdx.x * 8 + (threadIdx.x >> 5);
    int l = threadIdx.x & 31;
    float s = 0.0f;
    for (int j = l; j < 512; j += 32) s += W_y[row * 512 + j] * b_out[j];
#pragma unroll
    for (int off = 16; off; off >>= 1) s += __shfl_xor_sync(0xffffffffu, s, off);
    if (l == 0) c[row] = s + b_y[row];
}

// ---------------------------------------------------------------------------
// Warp matvec tile for the grid-barrier fallback (16 rows x 16 batches CTA).
// ---------------------------------------------------------------------------
__device__ __forceinline__ float matvec_tile(const float* __restrict__ sW,
                                             const float* __restrict__ sA,
                                             int kc, int bg2, int rg2) {
    const float* wp = sW + (rg2 * 8) * 512 + kc;
    const float* ap = sA + (bg2 * 4) * 512 + kc;
    float acc[32];
#pragma unroll
    for (int a = 0; a < 32; a++) acc[a] = 0.0f;
#pragma unroll
    for (int j = 0; j < 16; j++) {
        const int k = 32 * j;
        float yv[4], wv[8];
#pragma unroll
        for (int i2 = 0; i2 < 4; i2++) yv[i2] = ap[i2 * 512 + k];
#pragma unroll
        for (int p = 0; p < 8; p++) wv[p] = wp[p * 512 + k];
#pragma unroll
        for (int i2 = 0; i2 < 4; i2++)
#pragma unroll
            for (int p = 0; p < 8; p++)
                acc[i2 * 8 + p] = fmaf(yv[i2], wv[p], acc[i2 * 8 + p]);
    }
#pragma unroll
    for (int s = 16; s >= 1; s >>= 1) {
        const bool up = (kc & s);
#pragma unroll
        for (int a = 0; a < s; a++) {
            float send = up ? acc[a] : acc[a + s];
            float recv = __shfl_xor_sync(0xffffffffu, send, s);
            acc[a] = (up ? acc[a + s] : acc[a]) + recv;
        }
    }
    return acc[0];
}

extern __shared__ float smem[];

// ---------------------------------------------------------------------------
// Primary scan: h_t = tanh(xin_t + M h_{t-1} + c), 32 clusters x 4 CTAs.
// Cluster owns 2 batches; CTA owns 128 rows of M:
//   K [0,256)   -> SMEM  (128 KB)
//   K [256,512) -> registers (128 floats/thread)
// Warp w handles rows [w*16, w*16+16) x 2 batches; lanes split K 32-way.
// Double-buffered DSMEM h exchange, ONE cluster sync per step.
// ---------------------------------------------------------------------------
__global__ __launch_bounds__(256, 1) void jordan_scan_m_cluster4(
    float* __restrict__ out_h) {
    float* sW    = smem;                          // 128 rows x 256 K = 32768 f
    float* hbuf0 = smem + ROWS_C * KHALF;         // 2*512
    float* hbuf1 = hbuf0 + BPCL * 512;            // 2*512

    const int tid = threadIdx.x;
    unsigned rank;
    asm("mov.u32 %0, %%cluster_ctarank;" : "=r"(rank));
    const int cid = blockIdx.x / CSZ;
    const int b0 = cid * BPCL;
    const int r0row = (int)rank * ROWS_C;

    const int w = tid >> 5, kc = tid & 31;

    // SMEM weights: K-half [0,256) of this CTA's 128 rows.
    for (int q = tid; q < ROWS_C * KHALF / 4; q += 256) {
        int r = q >> 6;            // / (KHALF/4)
        int kq = q & 63;
        ((float4*)sW)[q] =
            ((const float4*)(g_M + (size_t)(r0row + r) * 512))[kq];
    }

    // Register weights: K-half [256,512): wreg[r2*8+j] = M[row, 256+kc+32j]
    float wreg[128];
#pragma unroll
    for (int r2 = 0; r2 < 16; r2++) {
        const float* mp = g_M + (size_t)(r0row + w * 16 + r2) * 512 + KHALF + kc;
#pragma unroll
        for (int j = 0; j < 8; j++) wreg[r2 * 8 + j] = mp[32 * j];
    }

    // Output mapping after tree-reduce: lane kc -> (row w*16 + (kc>>1), batch kc&1)
    const int row_l = w * 16 + (kc >> 1);
    const int b_l = kc & 1;
    const int b_idx = b0 + b_l;
    const int r_idx = r0row + row_l;
    const float cv = g_c[r_idx];

    uint32_t laddr[2];
    laddr[0] = smem_u32(&hbuf0[b_l * 512 + r_idx]);
    laddr[1] = smem_u32(&hbuf1[b_l * 512 + r_idx]);

    __syncthreads();
    cluster_sync();

    // t = 0: h_0 = tanh(xin_0 + r0)
    float xin_cur = g_xin[((size_t)b_idx * Tdim + 0) * Hdim + r_idx];
    {
        float v = tanhf(xin_cur + g_r0[(size_t)b_idx * 512 + r_idx]);
        out_h[((size_t)b_idx * Tdim + 0) * Hdim + r_idx] = v;
        xin_cur = g_xin[((size_t)b_idx * Tdim + 1) * Hdim + r_idx];
        push_all4(laddr[0], v);
        cluster_sync();
    }

    const float* sWrow = sW + (w * 16) * KHALF;   // this warp's 16 rows

    for (int t = 1; t < Tdim; t++) {
        const float* hb = ((t & 1) == 1) ? hbuf0 : hbuf1;  // h_{t-1}

        float acc[32];
#pragma unroll
        for (int a = 0; a < 32; a++) acc[a] = 0.0f;

        // K [0,256): weights from SMEM
#pragma unroll
        for (int j = 0; j < 8; j++) {
            const int k = kc + 32 * j;
            const float yv0 = hb[k];
            const float yv1 = hb[512 + k];
#pragma unroll
            for (int r2 = 0; r2 < 16; r2++) {
                const float wv = sWrow[r2 * KHALF + k];
                acc[r2 * 2 + 0] = fmaf(yv0, wv, acc[r2 * 2 + 0]);
                acc[r2 * 2 + 1] = fmaf(yv1, wv, acc[r2 * 2 + 1]);
            }
        }
        // K [256,512): weights from registers
#pragma unroll
        for (int j = 0; j < 8; j++) {
            const int k = KHALF + kc + 32 * j;
            const float yv0 = hb[k];
            const float yv1 = hb[512 + k];
#pragma unroll
            for (int r2 = 0; r2 < 16; r2++) {
                const float wv = wreg[r2 * 8 + j];
                acc[r2 * 2 + 0] = fmaf(yv0, wv, acc[r2 * 2 + 0]);
                acc[r2 * 2 + 1] = fmaf(yv1, wv, acc[r2 * 2 + 1]);
            }
        }
        // Tree reduce: lane l ends with total of acc[l].
#pragma unroll
        for (int s = 16; s >= 1; s >>= 1) {
            const bool up = (kc & s);
#pragma unroll
            for (int a = 0; a < s; a++) {
                float send = up ? acc[a] : acc[a + s];
                float recv = __shfl_xor_sync(0xffffffffu, send, s);
                acc[a] = (up ? acc[a + s] : acc[a]) + recv;
            }
        }

        float v = tanhf(acc[0] + xin_cur + cv);
        out_h[((size_t)b_idx * Tdim + t) * Hdim + r_idx] = v;
        if (t + 1 < Tdim)
            xin_cur = g_xin[((size_t)b_idx * Tdim + (t + 1)) * Hdim + r_idx];
        push_all4(laddr[t & 1], v);
        cluster_sync();
    }
}

// ---------------------------------------------------------------------------
// Fallback scan: grid barrier (128 CTAs), ONE barrier/step.
// ---------------------------------------------------------------------------
__global__ __launch_bounds__(256, 1) void jordan_scan_m(
    float* __restrict__ out_h) {
    float* sM   = smem;
    float* sAct = smem + RPB * 512;

    const int tid = threadIdx.x;
    const int bid = blockIdx.x;
    const int rg = bid & 31;
    const int bg = bid >> 5;
    const int r0 = rg * RPB;
    const int b0 = bg * BPB;

    for (int q = tid; q < RPB * 512 / 4; q += 256)
        ((float4*)sM)[q] = ((const float4*)(g_M + (size_t)r0 * 512))[q];

    const int w = tid >> 5, kc = tid & 31;
    const int bg2 = w >> 1, rg2 = w & 1;
    const int i2 = kc >> 3, p = kc & 7;
    const int b_idx = b0 + bg2 * 4 + i2;
    const int r_idx = r0 + rg2 * 8 + p;
    const float cv = g_c[r_idx];

    const int sb = tid >> 4;
    const int sc = tid & 15;

    __syncthreads();

    {
        float v = tanhf(g_xin[((size_t)b_idx * Tdim + 0) * Hdim + r_idx] +
                        g_r0[(size_t)b_idx * 512 + r_idx]);
        out_h[((size_t)b_idx * Tdim + 0) * Hdim + r_idx] = v;
    }
    __threadfence();
    gridbar();

    for (int t = 1; t < Tdim; t++) {
        {
            const float* src = out_h + ((size_t)(b0 + sb) * Tdim + (t - 1)) * Hdim;
            float4* dst = (float4*)(sAct + sb * 512);
            const float4* s4 = (const float4*)src;
#pragma unroll
            for (int q = 0; q < 8; q++) dst[sc + 16 * q] = s4[sc + 16 * q];
        }
        __syncthreads();

        float v = matvec_tile(sM, sAct, kc, bg2, rg2);
        v = tanhf(v + g_xin[((size_t)b_idx * Tdim + t) * Hdim + r_idx] + cv);
        out_h[((size_t)b_idx * Tdim + t) * Hdim + r_idx] = v;
        __threadfence();
        gridbar();
    }
}

// ---------------------------------------------------------------------------
extern "C" void kernel_launch(void* const* d_in, const int* in_sizes, int n_in,
                              void* d_out, int out_size) {
    const float* emb    = (const float*)d_in[0];
    const float* lastlg = (const float*)d_in[1];
    const float* W_in   = (const float*)d_in[2];
    const float* b_in   = (const float*)d_in[3];
    const float* W_y    = (const float*)d_in[4];
    const float* b_y    = (const float*)d_in[5];
    const float* W_out  = (const float*)d_in[6];
    const float* b_out  = (const float*)d_in[7];

    float* out    = (float*)d_out;
    float* out_h  = out;
    float* out_y  = out + (size_t)Bdim * Tdim * Hdim;
    float* out_yl = out + (size_t)2 * Bdim * Tdim * Hdim;

    float* xin_p; cudaGetSymbolAddress((void**)&xin_p, g_xin);
    float* M_p;   cudaGetSymbolAddress((void**)&M_p, g_M);
    float* r0_p;  cudaGetSymbolAddress((void**)&r0_p, g_r0);
    float* c_p;   cudaGetSymbolAddress((void**)&c_p, g_c);

    // Precomputes
    gemm_nn_M<<<dim3(512 / BN, 512 / BM), 256>>>(W_y, W_out, M_p);
    calc_c_kernel<<<64, 256>>>(W_y, b_y, b_out, c_p);
    gemm_nt<<<dim3(512 / BN, Bdim / BM), 256>>>(lastlg, W_y, b_y, r0_p, nullptr);

    // Input projection
    gemm_nt<<<dim3(512 / BN, (Bdim * Tdim) / BM), 256>>>(emb, W_in, b_in,
                                                          xin_p, nullptr);

    // ---- scan: try 4-CTA cluster path ----
    const int smem_cluster =
        (ROWS_C * KHALF + 2 * BPCL * 512) * (int)sizeof(float);  // 136 KB
    bool use_cluster =
        (cudaFuncSetAttribute(jordan_scan_m_cluster4,
                              cudaFuncAttributeMaxDynamicSharedMemorySize,
                              smem_cluster) == cudaSuccess);

    cudaLaunchConfig_t cfg = {};
    cfg.gridDim = dim3(CSZ * NCL, 1, 1);
    cfg.blockDim = dim3(256, 1, 1);
    cfg.dynamicSmemBytes = smem_cluster;
    cudaLaunchAttribute attrs[1];
    attrs[0].id = cudaLaunchAttributeClusterDimension;
    attrs[0].val.clusterDim.x = CSZ;
    attrs[0].val.clusterDim.y = 1;
    attrs[0].val.clusterDim.z = 1;
    cfg.attrs = attrs;
    cfg.numAttrs = 1;

    if (use_cluster) {
        int maxClusters = 0;
        cudaError_t st = cudaOccupancyMaxActiveClusters(&maxClusters,
                                                        jordan_scan_m_cluster4,
                                                        &cfg);
        if (st != cudaSuccess || maxClusters < NCL) use_cluster = false;
    }
    (void)cudaGetLastError();

    if (use_cluster) {
        cudaError_t st = cudaLaunchKernelEx(&cfg, jordan_scan_m_cluster4, out_h);
        if (st != cudaSuccess) {
            (void)cudaGetLastError();
            use_cluster = false;
        }
    }
    if (!use_cluster) {
        const int smem_fb = 2 * RPB * 512 * (int)sizeof(float);  // 64 KB
        cudaFuncSetAttribute(jordan_scan_m,
                             cudaFuncAttributeMaxDynamicSharedMemorySize, smem_fb);
        jordan_scan_m<<<NBLK, 256, smem_fb>>>(out_h);
    }

    // Epilogue: y = h @ W_out^T + b_out (+ y_last rows)
    gemm_nt<<<dim3(512 / BN, (Bdim * Tdim) / BM), 256>>>(out_h, W_out, b_out,
                                                          out_y, out_yl);
}